// round 2
// baseline (speedup 1.0000x reference)
#include <cuda_runtime.h>

#define B 384
#define DIM 1024

// Scratch in device globals (no allocations allowed).
__device__ float g_D[B * B];          // squared pairwise distances
__device__ float g_sq[B];             // per-row squared norms
__device__ int   g_lab[B];            // labels normalized to int32
__device__ double g_total;            // sum of relu losses
__device__ unsigned long long g_count; // number of valid triplets

// ---------------------------------------------------------------------------
// Kernel 0: normalize labels (detect int64 vs int32 storage) + zero accums.
// int64 little-endian non-negative labels => every odd int32 word is zero.
// For random int32 labels in [0,16), all-odd-words-zero has prob (1/16)^192.
// ---------------------------------------------------------------------------
__global__ void k_labels(const void* __restrict__ labp) {
    __shared__ int s_is64;
    int t = threadIdx.x;
    if (t == 0) {
        const int* p32 = (const int*)labp;
        int allzero = 1, anypos = 0;
        // Only inspect first 384 int32 words (1536B) — safe for both dtypes.
        for (int i = 0; i < B / 2; i++) {
            if (p32[2 * i + 1] != 0) allzero = 0;
            if (p32[2 * i] > 0) anypos = 1;
        }
        s_is64 = (allzero && anypos) ? 1 : 0;
        g_total = 0.0;
        g_count = 0ull;
    }
    __syncthreads();
    if (s_is64)
        g_lab[t] = (int)((const long long*)labp)[t];
    else
        g_lab[t] = ((const int*)labp)[t];
}

// ---------------------------------------------------------------------------
// Kernel 1: per-row squared norms.
// ---------------------------------------------------------------------------
__global__ void k_sq(const float* __restrict__ E) {
    __shared__ float red[256];
    int row = blockIdx.x;
    float s = 0.f;
    const float* rp = E + (size_t)row * DIM;
    for (int k = threadIdx.x; k < DIM; k += 256) {
        float v = rp[k];
        s += v * v;
    }
    red[threadIdx.x] = s;
    __syncthreads();
    for (int off = 128; off > 0; off >>= 1) {
        if (threadIdx.x < off) red[threadIdx.x] += red[threadIdx.x + off];
        __syncthreads();
    }
    if (threadIdx.x == 0) g_sq[row] = red[0];
}

// ---------------------------------------------------------------------------
// Kernel 2: D = sq_i + sq_j - 2 * E E^T   (32x32 smem-tiled fp32 GEMM).
// ---------------------------------------------------------------------------
__global__ void k_gram(const float* __restrict__ E) {
    __shared__ float As[32][33];
    __shared__ float Bs[32][33];
    int tx = threadIdx.x, ty = threadIdx.y;
    int row = blockIdx.y * 32 + ty;
    int colbase = blockIdx.x * 32;
    int col = colbase + tx;
    float acc = 0.f;
    for (int k0 = 0; k0 < DIM; k0 += 32) {
        As[ty][tx] = E[(size_t)row * DIM + k0 + tx];
        Bs[ty][tx] = E[(size_t)(colbase + ty) * DIM + k0 + tx];
        __syncthreads();
#pragma unroll
        for (int k = 0; k < 32; k++)
            acc += As[ty][k] * Bs[tx][k];
        __syncthreads();
    }
    g_D[row * B + col] = g_sq[row] + g_sq[col] - 2.f * acc;
}

// ---------------------------------------------------------------------------
// Kernel 3: per-anchor triplet accumulation.
// Block = anchor a; thread t = negative candidate n.
// loss contribution: for each p>a with lab[p]==lab[a], each n with lab[n]!=lab[a]:
//   relu(D[a,p] - D[a,n] + 1)
// ---------------------------------------------------------------------------
__global__ void k_loss() {
    __shared__ float  Drow[B];
    __shared__ int    lab[B];
    __shared__ double redd[B];
    __shared__ int    redi[B];

    int a = blockIdx.x;
    int t = threadIdx.x;

    Drow[t] = g_D[a * B + t];
    lab[t] = g_lab[t];
    __syncthreads();

    int la = lab[a];
    int is_neg = (lab[t] != la) ? 1 : 0;
    float d_an = Drow[t];

    float thr = 0.f;
    int npos = 0;
    for (int p = a + 1; p < B; p++) {
        if (lab[p] == la) {
            npos++;
            if (is_neg) {
                float v = Drow[p] - d_an + 1.0f;
                thr += (v > 0.f) ? v : 0.f;
            }
        }
    }

    redd[t] = (double)thr;
    redi[t] = is_neg;
    __syncthreads();
    // non-pow2-safe block reduce (B = 384)
    for (int off = 256; off > 0; off >>= 1) {
        if (t < off && t + off < B) {
            redd[t] += redd[t + off];
            redi[t] += redi[t + off];
        }
        __syncthreads();
    }
    if (t == 0) {
        if (redd[0] != 0.0) atomicAdd(&g_total, redd[0]);
        unsigned long long c = (unsigned long long)npos * (unsigned long long)redi[0];
        if (c) atomicAdd(&g_count, c);
    }
}

// ---------------------------------------------------------------------------
// Kernel 4: finalize mean (+count if requested).
// ---------------------------------------------------------------------------
__global__ void k_final(float* __restrict__ out, int out_size) {
    double mean = (g_count > 0) ? (g_total / (double)g_count) : 0.0;
    if (out_size >= 1) out[0] = (float)mean;
    if (out_size >= 2) out[1] = (float)g_count;
}

extern "C" void kernel_launch(void* const* d_in, const int* in_sizes, int n_in,
                              void* d_out, int out_size) {
    const float* E = (const float*)d_in[0];
    const void* labels = d_in[1];
    float* out = (float*)d_out;

    k_labels<<<1, B>>>(labels);
    k_sq<<<B, 256>>>(E);
    {
        dim3 grid(B / 32, B / 32);
        dim3 blk(32, 32);
        k_gram<<<grid, blk>>>(E);
    }
    k_loss<<<B, B>>>();
    k_final<<<1, 1>>>(out, out_size);
}

// round 3
// speedup vs baseline: 2.0151x; 2.0151x over previous
#include <cuda_runtime.h>

#define B   384
#define DIM 1024

// Scratch in device globals (no allocations allowed).
__device__ float  g_G[B * B];           // Gram matrix E E^T
__device__ float  g_sq[B];              // diag(G) = squared norms
__device__ double g_total;              // sum of relu losses
__device__ unsigned long long g_count;  // number of valid triplets
__device__ unsigned int g_done;         // block completion counter

// ---------------------------------------------------------------------------
// Kernel 1: Gram matrix  G = E E^T  (fp32, 32x32 tile, 2x2 register micro).
// 144 blocks of 256 threads (16x16), full-chip, FFMA-rate bound.
// Diagonal tiles also write g_sq. Block (0,0) zeroes the accumulators.
// ---------------------------------------------------------------------------
__global__ void k_gram(const float* __restrict__ E) {
    __shared__ float As[32][33];   // As[i][k] = E[row0+i][k0+k]
    __shared__ float Bs[32][33];   // Bs[j][k] = E[col0+j][k0+k]

    const int tid = threadIdx.x;         // 0..255
    const int tx = tid & 15;             // 0..15  (col pair)
    const int ty = tid >> 4;             // 0..15  (row pair)
    const int row0 = blockIdx.y * 32;
    const int col0 = blockIdx.x * 32;

    // Loader mapping: coalesced float4 along k.
    const int li = tid >> 3;             // 0..31 row within panel
    const int lk = (tid & 7) * 4;        // 0,4,...,28
    const float* Ea = E + (size_t)(row0 + li) * DIM + lk;
    const float* Eb = E + (size_t)(col0 + li) * DIM + lk;

    if (blockIdx.x == 0 && blockIdx.y == 0 && tid == 0) {
        g_total = 0.0;
        g_count = 0ull;
        g_done  = 0u;
    }

    float acc00 = 0.f, acc01 = 0.f, acc10 = 0.f, acc11 = 0.f;

    for (int k0 = 0; k0 < DIM; k0 += 32) {
        float4 a = *(const float4*)(Ea + k0);
        float4 b = *(const float4*)(Eb + k0);
        // scalar STS, conflict-free with pad 33: bank = (li + lk + u) % 32 distinct
        As[li][lk + 0] = a.x; As[li][lk + 1] = a.y;
        As[li][lk + 2] = a.z; As[li][lk + 3] = a.w;
        Bs[li][lk + 0] = b.x; Bs[li][lk + 1] = b.y;
        Bs[li][lk + 2] = b.z; Bs[li][lk + 3] = b.w;
        __syncthreads();
#pragma unroll
        for (int k = 0; k < 32; k++) {
            float a0 = As[2 * ty][k];
            float a1 = As[2 * ty + 1][k];
            float b0 = Bs[2 * tx][k];
            float b1 = Bs[2 * tx + 1][k];
            acc00 += a0 * b0; acc01 += a0 * b1;
            acc10 += a1 * b0; acc11 += a1 * b1;
        }
        __syncthreads();
    }

    const int r = row0 + 2 * ty;
    const int c = col0 + 2 * tx;
    g_G[r * B + c]           = acc00;
    g_G[r * B + c + 1]       = acc01;
    g_G[(r + 1) * B + c]     = acc10;
    g_G[(r + 1) * B + c + 1] = acc11;

    if (blockIdx.x == blockIdx.y && ty == tx) {
        g_sq[r]     = acc00;   // G[r][r]
        g_sq[r + 1] = acc11;   // G[r+1][r+1]
    }
}

// ---------------------------------------------------------------------------
// Kernel 2: per-anchor triplet loss with compressed positive list,
// fused label parsing (int64/int32 autodetect) and fused finalize.
// Block = anchor a; thread t = negative candidate n.
//   D[a,j] - D[a,n]  =  (sq_j - 2 G[a,j]) - (sq_n - 2 G[a,n])   (sq_a cancels)
// ---------------------------------------------------------------------------
__global__ void k_loss(const void* __restrict__ labp,
                       float* __restrict__ out, int out_size) {
    __shared__ float  Drow[B];
    __shared__ int    lab[B];
    __shared__ float  P[B];        // compressed positive distances
    __shared__ int    s_npos;
    __shared__ double s_warp[12];
    __shared__ int    s_last;

    const int a = blockIdx.x;
    const int t = threadIdx.x;
    const int lane = t & 31;
    const int wid  = t >> 5;

    // --- label dtype detection: inspect only the first 1536 bytes (safe for
    // both int32[384] and int64[384] buffers). int64 non-neg => odd words 0.
    const int* p32 = (const int*)labp;
    int w = p32[t];
    int odd_ok = (t & 1) ? (w == 0) : 1;
    int anypos = (!(t & 1)) && (w > 0);
    int allz  = __syncthreads_and(odd_ok);
    int anyp  = __syncthreads_or(anypos);
    int is64  = allz && anyp;

    lab[t] = is64 ? (int)((const long long*)labp)[t] : p32[t];
    Drow[t] = g_sq[t] - 2.0f * g_G[a * B + t];
    if (t == 0) s_npos = 0;
    __syncthreads();

    const int la = lab[a];
    const int is_neg = (lab[t] != la);

    // --- warp-aggregated compaction of positives p > a with lab[p]==la
    {
        int ispos = (t > a) && (lab[t] == la);
        unsigned m = __ballot_sync(0xffffffffu, ispos);
        int base = 0;
        if (m) {
            if (lane == 0) base = atomicAdd(&s_npos, __popc(m));
            base = __shfl_sync(0xffffffffu, base, 0);
            if (ispos) P[base + __popc(m & ((1u << lane) - 1u))] = Drow[t];
        }
    }
    // barrier (also publishes s_npos and P); count negatives while at it
    const int nneg = __syncthreads_count(is_neg);
    const int npos = s_npos;

    // --- hot loop: ~npos (avg ~12) iterations per negative thread
    float acc = 0.f;
    if (is_neg && npos > 0) {
        const float cadd = 1.0f - Drow[t];   // margin - D[a,n]
        for (int j = 0; j < npos; j++) {
            float v = P[j] + cadd;
            acc += (v > 0.f) ? v : 0.f;
        }
    }

    // --- block reduce: warp shuffle (float), then double across 12 warps
#pragma unroll
    for (int off = 16; off > 0; off >>= 1)
        acc += __shfl_down_sync(0xffffffffu, acc, off);
    if (lane == 0) s_warp[wid] = (double)acc;
    __syncthreads();

    if (t == 0) {
        double tot = 0.0;
        for (int i = 0; i < 12; i++) tot += s_warp[i];
        if (tot != 0.0) atomicAdd(&g_total, tot);
        unsigned long long cnt =
            (unsigned long long)npos * (unsigned long long)nneg;
        if (cnt) atomicAdd(&g_count, cnt);
        __threadfence();
        unsigned old = atomicInc(&g_done, 0xffffffffu);
        s_last = (old == (unsigned)(B - 1));
    }
    __syncthreads();

    // --- last block finalizes
    if (s_last && t == 0) {
        __threadfence();
        double tot = atomicAdd(&g_total, 0.0);
        unsigned long long cnt = atomicAdd(&g_count, 0ull);
        double mean = (cnt > 0) ? (tot / (double)cnt) : 0.0;
        if (out_size >= 1) out[0] = (float)mean;
        if (out_size >= 2) out[1] = (float)cnt;
    }
}

extern "C" void kernel_launch(void* const* d_in, const int* in_sizes, int n_in,
                              void* d_out, int out_size) {
    const float* E = (const float*)d_in[0];
    const void* labels = d_in[1];
    float* out = (float*)d_out;

    dim3 grid(B / 32, B / 32);
    k_gram<<<grid, 256>>>(E);
    k_loss<<<B, B>>>(labels, out, out_size);
}

// round 9
// speedup vs baseline: 2.1728x; 1.0783x over previous
#include <cuda_runtime.h>

#define B    384
#define DIM  1024
#define LBLK 144
#define LTHR 256

typedef unsigned long long ull;

// Scratch in device globals (no allocations allowed).
__device__ float  g_G[B * B];           // Gram matrix E E^T
__device__ float  g_sq[B];              // diag(G)
__device__ double g_total;
__device__ unsigned long long g_count;
__device__ unsigned int g_done;

// Staggered smem layout (float2 units): row j starts at j*17 + (j>>4).
// Even rows (2tx) at equal kk hit 16 distinct bank-pairs -> conflict-free LDS.64.
__device__ __forceinline__ int soff(int j, int kk) {
    return j * 17 + (j >> 4) + kk;
}

// Packed dual fp32 FMA (SASS FFMA2) — only reachable via PTX.
__device__ __forceinline__ void ffma2(ull& acc, ull a, ull b) {
    asm("fma.rn.f32x2 %0, %1, %2, %0;" : "+l"(acc) : "l"(a), "l"(b));
}

__device__ __forceinline__ float unpack_sum(ull v) {
    float lo = __uint_as_float((unsigned)(v & 0xffffffffull));
    float hi = __uint_as_float((unsigned)(v >> 32));
    return lo + hi;   // even-k partial + odd-k partial
}

// ---------------------------------------------------------------------------
// Kernel 1: Gram 32x32 tiles, FFMA2 over k-pairs, 144 blocks x 256 threads.
// Block 0 also resets the global accumulators (stream order guarantees this
// completes before k_loss runs).
// ---------------------------------------------------------------------------
__global__ void __launch_bounds__(256, 1)
k_gram(const float* __restrict__ E) {
    __shared__ float2 SA[546];
    __shared__ float2 SB[546];

    const int tid = threadIdx.x;
    const int bty = blockIdx.y, btx = blockIdx.x;
    const int row0 = bty * 32, col0 = btx * 32;

    if (btx == 0 && bty == 0 && tid == 0) {
        g_total = 0.0;
        g_count = 0ull;
        g_done  = 0u;
    }

    const int tx = tid & 15, ty = tid >> 4;
    const int li = tid >> 3;               // loader row 0..31
    const float* Ea = E + (size_t)(row0 + li) * DIM + (tid & 7) * 4;
    const float* Eb = E + (size_t)(col0 + li) * DIM + (tid & 7) * 4;

    const int st0 = soff(li, (tid & 7) * 2);
    const int a0o = soff(2 * ty, 0),  a1o = soff(2 * ty + 1, 0);
    const int b0o = soff(2 * tx, 0),  b1o = soff(2 * tx + 1, 0);
    const ull* SAu = (const ull*)SA;
    const ull* SBu = (const ull*)SB;

    ull acc00 = 0ull, acc01 = 0ull, acc10 = 0ull, acc11 = 0ull;

    float4 pa = *(const float4*)(Ea);
    float4 pb = *(const float4*)(Eb);

    for (int k0 = 0; k0 < DIM; k0 += 32) {
        __syncthreads();
        SA[st0]     = make_float2(pa.x, pa.y);
        SA[st0 + 1] = make_float2(pa.z, pa.w);
        SB[st0]     = make_float2(pb.x, pb.y);
        SB[st0 + 1] = make_float2(pb.z, pb.w);
        __syncthreads();
        if (k0 + 32 < DIM) {               // prefetch next tile during compute
            pa = *(const float4*)(Ea + k0 + 32);
            pb = *(const float4*)(Eb + k0 + 32);
        }
#pragma unroll
        for (int kk = 0; kk < 16; kk++) {
            ull a0 = SAu[a0o + kk];
            ull a1 = SAu[a1o + kk];
            ull b0 = SBu[b0o + kk];
            ull b1 = SBu[b1o + kk];
            ffma2(acc00, a0, b0);
            ffma2(acc01, a0, b1);
            ffma2(acc10, a1, b0);
            ffma2(acc11, a1, b1);
        }
    }

    const float v00 = unpack_sum(acc00), v01 = unpack_sum(acc01);
    const float v10 = unpack_sum(acc10), v11 = unpack_sum(acc11);
    const int r = row0 + 2 * ty;
    const int c = col0 + 2 * tx;
    g_G[r * B + c]           = v00;
    g_G[r * B + c + 1]       = v01;
    g_G[(r + 1) * B + c]     = v10;
    g_G[(r + 1) * B + c + 1] = v11;
    if (bty == btx && ty == tx) {
        g_sq[r]     = v00;                 // diag = squared norm
        g_sq[r + 1] = v11;
    }
}

// ---------------------------------------------------------------------------
// Kernel 2: triplet loss. 144 blocks x 256 threads, grid-stride over anchors.
//   D[a,j] - D[a,n] = (sq_j - 2 G[a,j]) - (sq_n - 2 G[a,n])   (sq_a cancels)
// Fused label parse (int64/int32 autodetect) and last-block finalize.
// ---------------------------------------------------------------------------
__global__ void __launch_bounds__(LTHR, 1)
k_loss(const void* __restrict__ labp, float* __restrict__ out, int out_size) {
    __shared__ float  Drow[B];
    __shared__ int    lab[B];
    __shared__ float  P[B];
    __shared__ int    s_npos;
    __shared__ double s_red[8];
    __shared__ int    s_redi[8];
    __shared__ int    s_last;

    const int tid = threadIdx.x;
    const int bx  = blockIdx.x;
    const int lane = tid & 31, wid = tid >> 5;

    // Label dtype detect on first 1536 bytes (valid for int32[384] & int64[384]):
    // int64 non-negative => odd int32 words are all zero.
    const int* p32 = (const int*)labp;
    int ok = 1, ap = 0;
    for (int w = tid; w < B; w += LTHR) {
        int v = p32[w];
        if (w & 1) { if (v != 0) ok = 0; }
        else       { if (v > 0)  ap = 1; }
    }
    const int allz = __syncthreads_and(ok);
    const int anyp = __syncthreads_or(ap);
    const int is64 = allz && anyp;
    for (int j = tid; j < B; j += LTHR)
        lab[j] = is64 ? (int)((const long long*)labp)[j] : p32[j];
    __syncthreads();

    double bl_tot = 0.0;
    ull    bl_cnt = 0ull;

    for (int a = bx; a < B; a += LBLK) {
        if (tid == 0) s_npos = 0;
        __syncthreads();
        const int la = lab[a];
#pragma unroll
        for (int rr = 0; rr < 2; rr++) {
            int j = tid + rr * LTHR;
            if (j < B) {
                float d = g_sq[j] - 2.0f * g_G[a * B + j];
                Drow[j] = d;
                if (j > a && lab[j] == la)
                    P[atomicAdd(&s_npos, 1)] = d;   // unordered compaction OK
            }
        }
        __syncthreads();
        const int npos = s_npos;

        float acc = 0.f;
        int negc = 0;
#pragma unroll
        for (int rr = 0; rr < 2; rr++) {
            int j = tid + rr * LTHR;
            if (j < B && lab[j] != la) {
                negc++;
                const float cadd = 1.0f - Drow[j];  // margin - D[a,n]
                for (int q = 0; q < npos; q++) {
                    float v = P[q] + cadd;
                    acc += (v > 0.f) ? v : 0.f;
                }
            }
        }
#pragma unroll
        for (int off = 16; off > 0; off >>= 1) {
            acc  += __shfl_down_sync(0xffffffffu, acc, off);
            negc += __shfl_down_sync(0xffffffffu, negc, off);
        }
        if (lane == 0) { s_red[wid] = (double)acc; s_redi[wid] = negc; }
        __syncthreads();
        if (tid == 0) {
            double tt = 0.0; int nn = 0;
            for (int i = 0; i < 8; i++) { tt += s_red[i]; nn += s_redi[i]; }
            bl_tot += tt;
            bl_cnt += (ull)npos * (ull)nn;
        }
        __syncthreads();                    // before Drow/P reuse
    }

    if (tid == 0) {
        if (bl_tot != 0.0) atomicAdd(&g_total, bl_tot);
        if (bl_cnt)        atomicAdd(&g_count, bl_cnt);
        __threadfence();
        unsigned old = atomicInc(&g_done, 0xffffffffu);
        s_last = (old == (unsigned)(LBLK - 1));
    }
    __syncthreads();

    if (s_last && tid == 0) {
        double tot = atomicAdd(&g_total, 0.0);          // coherent L2 read
        ull    cnt = atomicAdd(&g_count, 0ull);
        double mean = (cnt > 0) ? (tot / (double)cnt) : 0.0;
        if (out_size >= 1) out[0] = (float)mean;
        if (out_size >= 2) out[1] = (float)cnt;
    }
}

extern "C" void kernel_launch(void* const* d_in, const int* in_sizes, int n_in,
                              void* d_out, int out_size) {
    const float* E = (const float*)d_in[0];
    const void* labels = d_in[1];
    float* out = (float*)d_out;

    dim3 grid(12, 12);
    k_gram<<<grid, 256>>>(E);
    k_loss<<<LBLK, LTHR>>>(labels, out, out_size);
}

// round 10
// speedup vs baseline: 2.3854x; 1.0979x over previous
#include <cuda_runtime.h>

#define B    384
#define DIM  1024

typedef unsigned long long ull;

// Scratch in device globals (no allocations allowed).
__device__ float  g_G[B * B];           // Gram matrix E E^T
__device__ float  g_sq[B];              // diag(G)
__device__ int    g_lab[B];             // labels normalized to int32
__device__ double g_total;
__device__ ull    g_count;
__device__ unsigned int g_done;

// Staggered smem layout (float2 units): row j starts at j*17 + (j>>4).
// b-rows (2tx) at equal kk hit 16 distinct bank-pairs; a-rows broadcast.
__device__ __forceinline__ int soff(int j, int kk) {
    return j * 17 + (j >> 4) + kk;
}

// Packed dual fp32 FMA (SASS FFMA2) — only reachable via PTX.
__device__ __forceinline__ void ffma2(ull& acc, ull a, ull b) {
    asm("fma.rn.f32x2 %0, %1, %2, %0;" : "+l"(acc) : "l"(a), "l"(b));
}

__device__ __forceinline__ float unpack_sum(ull v) {
    float lo = __uint_as_float((unsigned)(v & 0xffffffffull));
    float hi = __uint_as_float((unsigned)(v >> 32));
    return lo + hi;   // even-k partial + odd-k partial
}

// ---------------------------------------------------------------------------
// Kernel 1: Gram 32x32 tiles, FFMA2, 2-deep LDG pipeline + double-buffer smem.
// Block (0,0) also resets accumulators and parses labels into g_lab.
// ---------------------------------------------------------------------------
__global__ void __launch_bounds__(256, 1)
k_gram(const float* __restrict__ E, const void* __restrict__ labp) {
    __shared__ float2 SA[2][546];
    __shared__ float2 SB[2][546];

    const int tid = threadIdx.x;
    const int bty = blockIdx.y, btx = blockIdx.x;
    const int row0 = bty * 32, col0 = btx * 32;

    if (btx == 0 && bty == 0 && tid == 0) {
        g_total = 0.0;
        g_count = 0ull;
        g_done  = 0u;
    }

    const int tx = tid & 15, ty = tid >> 4;
    const int li = tid >> 3;                       // loader row 0..31
    const float* Ea = E + (size_t)(row0 + li) * DIM + (tid & 7) * 4;
    const float* Eb = E + (size_t)(col0 + li) * DIM + (tid & 7) * 4;

    const int st0 = soff(li, (tid & 7) * 2);
    const int a0o = soff(2 * ty, 0),  a1o = soff(2 * ty + 1, 0);
    const int b0o = soff(2 * tx, 0),  b1o = soff(2 * tx + 1, 0);

    ull acc00 = 0ull, acc01 = 0ull, acc10 = 0ull, acc11 = 0ull;

    // 2-deep register prefetch pipeline: tile i lives in regs[i&1].
    float4 ra[2], rb[2];
    ra[0] = *(const float4*)(Ea);            rb[0] = *(const float4*)(Eb);
    ra[1] = *(const float4*)(Ea + 32);       rb[1] = *(const float4*)(Eb + 32);

    SA[0][st0]     = make_float2(ra[0].x, ra[0].y);
    SA[0][st0 + 1] = make_float2(ra[0].z, ra[0].w);
    SB[0][st0]     = make_float2(rb[0].x, rb[0].y);
    SB[0][st0 + 1] = make_float2(rb[0].z, rb[0].w);
    __syncthreads();

#pragma unroll 2
    for (int it = 0; it < 32; it++) {
        // Stage tile it+1 (its regs arrived >= 1 full compute iter ago).
        if (it + 1 < 32) {
            const int nb = (it + 1) & 1;
            SA[nb][st0]     = make_float2(ra[nb].x, ra[nb].y);
            SA[nb][st0 + 1] = make_float2(ra[nb].z, ra[nb].w);
            SB[nb][st0]     = make_float2(rb[nb].x, rb[nb].y);
            SB[nb][st0 + 1] = make_float2(rb[nb].z, rb[nb].w);
        }
        // Issue LDG for tile it+2 into the just-freed reg slot.
        if (it + 2 < 32) {
            ra[it & 1] = *(const float4*)(Ea + (it + 2) * 32);
            rb[it & 1] = *(const float4*)(Eb + (it + 2) * 32);
        }
        // Compute on current buffer.
        const ull* SAu = (const ull*)SA[it & 1];
        const ull* SBu = (const ull*)SB[it & 1];
#pragma unroll
        for (int kk = 0; kk < 16; kk++) {
            ull a0 = SAu[a0o + kk];
            ull a1 = SAu[a1o + kk];
            ull b0 = SBu[b0o + kk];
            ull b1 = SBu[b1o + kk];
            ffma2(acc00, a0, b0);
            ffma2(acc01, a0, b1);
            ffma2(acc10, a1, b0);
            ffma2(acc11, a1, b1);
        }
        __syncthreads();
    }

    const float v00 = unpack_sum(acc00), v01 = unpack_sum(acc01);
    const float v10 = unpack_sum(acc10), v11 = unpack_sum(acc11);
    const int r = row0 + 2 * ty;
    const int c = col0 + 2 * tx;
    g_G[r * B + c]           = v00;
    g_G[r * B + c + 1]       = v01;
    g_G[(r + 1) * B + c]     = v10;
    g_G[(r + 1) * B + c + 1] = v11;
    if (bty == btx && ty == tx) {
        g_sq[r]     = v00;                 // diag = squared norm
        g_sq[r + 1] = v11;
    }

    // --- Label parse (block (0,0) only; all 256 threads participate) -------
    // Detect int64 vs int32 on the first 1536 bytes (valid for both layouts):
    // non-negative little-endian int64 => odd int32 words are all zero.
    if (btx == 0 && bty == 0) {
        const int* p32 = (const int*)labp;
        int ok = 1, ap = 0;
        for (int w = tid; w < B; w += 256) {
            int v = p32[w];
            if (w & 1) { if (v != 0) ok = 0; }
            else       { if (v > 0)  ap = 1; }
        }
        const int allz = __syncthreads_and(ok);
        const int anyp = __syncthreads_or(ap);
        const int is64 = allz && anyp;
        for (int j = tid; j < B; j += 256)
            g_lab[j] = is64 ? (int)((const long long*)labp)[j] : p32[j];
    }
}

// ---------------------------------------------------------------------------
// Kernel 2: triplet loss. One block per anchor, 384 threads (thread = negative
// candidate).  D[a,j]-D[a,n] = (sq_j - 2G[a,j]) - (sq_n - 2G[a,n]); sq_a cancels.
// ---------------------------------------------------------------------------
__global__ void __launch_bounds__(B)
k_loss(float* __restrict__ out, int out_size) {
    __shared__ float  P[B];        // compressed positive distances
    __shared__ int    s_npos;
    __shared__ double s_red[12];

    const int a = blockIdx.x;
    const int t = threadIdx.x;
    const int lane = t & 31, wid = t >> 5;

    // Issue all long-latency loads before touching barriers.
    const float gv = g_G[a * B + t];
    const float sq = g_sq[t];
    const int   lt = g_lab[t];
    const int   la = g_lab[a];          // warp-uniform broadcast load

    if (t == 0) s_npos = 0;
    __syncthreads();

    const float d = sq - 2.0f * gv;
    const int ispos = (t > a) && (lt == la);

    // Warp-aggregated compaction of positives into P.
    unsigned m = __ballot_sync(0xffffffffu, ispos);
    if (m) {
        int base = 0;
        if (lane == 0) base = atomicAdd(&s_npos, __popc(m));
        base = __shfl_sync(0xffffffffu, base, 0);
        if (ispos) P[base + __popc(m & ((1u << lane) - 1u))] = d;
    }
    const int is_neg = (lt != la);
    const int nneg = __syncthreads_count(is_neg);   // barrier publishes P/s_npos
    const int npos = s_npos;

    float acc = 0.f;
    if (is_neg && npos > 0) {
        const float cadd = 1.0f - d;    // margin - D[a,n]
        for (int q = 0; q < npos; q++) {
            float v = P[q] + cadd;
            acc += (v > 0.f) ? v : 0.f;
        }
    }

#pragma unroll
    for (int off = 16; off > 0; off >>= 1)
        acc += __shfl_down_sync(0xffffffffu, acc, off);
    if (lane == 0) s_red[wid] = (double)acc;
    __syncthreads();

    if (t == 0) {
        double tot = 0.0;
        for (int i = 0; i < 12; i++) tot += s_red[i];
        if (tot != 0.0) atomicAdd(&g_total, tot);
        ull cnt = (ull)npos * (ull)nneg;
        if (cnt) atomicAdd(&g_count, cnt);
        __threadfence();
        if (atomicInc(&g_done, 0xffffffffu) == (unsigned)(B - 1)) {
            double tt = atomicAdd(&g_total, 0.0);       // coherent reads
            ull    cc = atomicAdd(&g_count, 0ull);
            double mean = (cc > 0) ? (tt / (double)cc) : 0.0;
            if (out_size >= 1) out[0] = (float)mean;
            if (out_size >= 2) out[1] = (float)cc;
        }
    }
}

extern "C" void kernel_launch(void* const* d_in, const int* in_sizes, int n_in,
                              void* d_out, int out_size) {
    const float* E = (const float*)d_in[0];
    const void* labels = d_in[1];
    float* out = (float*)d_out;

    dim3 grid(12, 12);
    k_gram<<<grid, 256>>>(E, labels);
    k_loss<<<B, B>>>(out, out_size);
}

// round 11
// speedup vs baseline: 2.5497x; 1.0689x over previous
#include <cuda_runtime.h>

#define B      384
#define DIM    1024
#define SPLITK 4
#define KPB    (DIM / SPLITK)   // 256 k per gram block
#define NIT    (KPB / 32)       // 8 tiles of 32

typedef unsigned long long ull;

// Scratch in device globals (no allocations allowed).
__device__ float  g_Gp[SPLITK][B * B];   // partial Gram matrices per K-split
__device__ float  g_sqp[SPLITK][B];      // partial diagonals
__device__ int    g_lab[B];              // labels normalized to int32
__device__ double g_ptot[B];             // per-anchor loss partials
__device__ ull    g_pcnt[B];             // per-anchor triplet counts
__device__ unsigned int g_done;

// Staggered smem layout (float2 units): row j starts at j*17 + (j>>4).
// b-rows (2tx) at equal kk hit 16 distinct bank-pairs; a-rows broadcast.
__device__ __forceinline__ int soff(int j, int kk) {
    return j * 17 + (j >> 4) + kk;
}

// Packed dual fp32 FMA (SASS FFMA2) — only reachable via PTX.
__device__ __forceinline__ void ffma2(ull& acc, ull a, ull b) {
    asm("fma.rn.f32x2 %0, %1, %2, %0;" : "+l"(acc) : "l"(a), "l"(b));
}

__device__ __forceinline__ float unpack_sum(ull v) {
    float lo = __uint_as_float((unsigned)(v & 0xffffffffull));
    float hi = __uint_as_float((unsigned)(v >> 32));
    return lo + hi;   // even-k partial + odd-k partial
}

// ---------------------------------------------------------------------------
// Kernel 1: split-K Gram. grid (12,12,SPLITK); block z computes K range
// [z*256,(z+1)*256) of its 32x32 tile into g_Gp[z]. 4 blocks co-resident/SM.
// ---------------------------------------------------------------------------
__global__ void __launch_bounds__(256, 4)
k_gram(const float* __restrict__ E, const void* __restrict__ labp) {
    __shared__ float2 SA[2][546];
    __shared__ float2 SB[2][546];

    const int tid = threadIdx.x;
    const int bty = blockIdx.y, btx = blockIdx.x, kz = blockIdx.z;
    const int row0 = bty * 32, col0 = btx * 32;

    if (btx == 0 && bty == 0 && kz == 0 && tid == 0) g_done = 0u;

    const int tx = tid & 15, ty = tid >> 4;
    const int li = tid >> 3;                       // loader row 0..31
    const float* Ea = E + (size_t)(row0 + li) * DIM + kz * KPB + (tid & 7) * 4;
    const float* Eb = E + (size_t)(col0 + li) * DIM + kz * KPB + (tid & 7) * 4;

    const int st0 = soff(li, (tid & 7) * 2);
    const int a0o = soff(2 * ty, 0),  a1o = soff(2 * ty + 1, 0);
    const int b0o = soff(2 * tx, 0),  b1o = soff(2 * tx + 1, 0);

    ull acc00 = 0ull, acc01 = 0ull, acc10 = 0ull, acc11 = 0ull;

    // 2-deep register prefetch pipeline.
    float4 ra[2], rb[2];
    ra[0] = *(const float4*)(Ea);            rb[0] = *(const float4*)(Eb);
    ra[1] = *(const float4*)(Ea + 32);       rb[1] = *(const float4*)(Eb + 32);

    SA[0][st0]     = make_float2(ra[0].x, ra[0].y);
    SA[0][st0 + 1] = make_float2(ra[0].z, ra[0].w);
    SB[0][st0]     = make_float2(rb[0].x, rb[0].y);
    SB[0][st0 + 1] = make_float2(rb[0].z, rb[0].w);
    __syncthreads();

#pragma unroll 2
    for (int it = 0; it < NIT; it++) {
        if (it + 1 < NIT) {                 // stage next tile (regs are ready)
            const int nb = (it + 1) & 1;
            SA[nb][st0]     = make_float2(ra[nb].x, ra[nb].y);
            SA[nb][st0 + 1] = make_float2(ra[nb].z, ra[nb].w);
            SB[nb][st0]     = make_float2(rb[nb].x, rb[nb].y);
            SB[nb][st0 + 1] = make_float2(rb[nb].z, rb[nb].w);
        }
        if (it + 2 < NIT) {                 // LDG tile it+2 into freed slot
            ra[it & 1] = *(const float4*)(Ea + (it + 2) * 32);
            rb[it & 1] = *(const float4*)(Eb + (it + 2) * 32);
        }
        const ull* SAu = (const ull*)SA[it & 1];
        const ull* SBu = (const ull*)SB[it & 1];
#pragma unroll
        for (int kk = 0; kk < 16; kk++) {
            ull a0 = SAu[a0o + kk];
            ull a1 = SAu[a1o + kk];
            ull b0 = SBu[b0o + kk];
            ull b1 = SBu[b1o + kk];
            ffma2(acc00, a0, b0);
            ffma2(acc01, a0, b1);
            ffma2(acc10, a1, b0);
            ffma2(acc11, a1, b1);
        }
        __syncthreads();
    }

    const float v00 = unpack_sum(acc00), v01 = unpack_sum(acc01);
    const float v10 = unpack_sum(acc10), v11 = unpack_sum(acc11);
    const int r = row0 + 2 * ty;
    const int c = col0 + 2 * tx;
    float* Gz = g_Gp[kz];
    *(float2*)(Gz + r * B + c)       = make_float2(v00, v01);
    *(float2*)(Gz + (r + 1) * B + c) = make_float2(v10, v11);
    if (bty == btx && ty == tx) {
        g_sqp[kz][r]     = v00;            // diag partial
        g_sqp[kz][r + 1] = v11;
    }

    // --- Label parse (block (0,0,0) only). Detect int64 vs int32 on the
    // first 1536 bytes: non-negative LE int64 => odd int32 words all zero.
    if (btx == 0 && bty == 0 && kz == 0) {
        const int* p32 = (const int*)labp;
        int ok = 1, ap = 0;
        for (int w = tid; w < B; w += 256) {
            int v = p32[w];
            if (w & 1) { if (v != 0) ok = 0; }
            else       { if (v > 0)  ap = 1; }
        }
        const int allz = __syncthreads_and(ok);
        const int anyp = __syncthreads_or(ap);
        const int is64 = allz && anyp;
        for (int j = tid; j < B; j += 256)
            g_lab[j] = is64 ? (int)((const long long*)labp)[j] : p32[j];
    }
}

// ---------------------------------------------------------------------------
// Kernel 2: triplet loss. One block per anchor, 384 threads. Per-block
// partials stored to distinct addresses; last block parallel-reduces them.
//   D[a,j]-D[a,n] = (sq_j - 2G[a,j]) - (sq_n - 2G[a,n]); sq_a cancels.
// ---------------------------------------------------------------------------
__global__ void __launch_bounds__(B)
k_loss(float* __restrict__ out, int out_size) {
    __shared__ float  P[B];
    __shared__ int    s_npos;
    __shared__ double s_red[12];
    __shared__ ull    s_redc[12];
    __shared__ int    s_last;

    const int a = blockIdx.x;
    const int t = threadIdx.x;
    const int lane = t & 31, wid = t >> 5;

    // Issue all long-latency loads up front (MLP hides the 4-way split).
    float gv = 0.f, sq = 0.f;
#pragma unroll
    for (int kz = 0; kz < SPLITK; kz++) {
        gv += g_Gp[kz][a * B + t];
        sq += g_sqp[kz][t];
    }
    const int lt = g_lab[t];
    const int la = g_lab[a];            // warp-uniform broadcast load

    if (t == 0) s_npos = 0;
    __syncthreads();

    const float d = sq - 2.0f * gv;
    const int ispos = (t > a) && (lt == la);

    // Warp-aggregated compaction of positives into P.
    unsigned m = __ballot_sync(0xffffffffu, ispos);
    if (m) {
        int base = 0;
        if (lane == 0) base = atomicAdd(&s_npos, __popc(m));
        base = __shfl_sync(0xffffffffu, base, 0);
        if (ispos) P[base + __popc(m & ((1u << lane) - 1u))] = d;
    }
    const int is_neg = (lt != la);
    const int nneg = __syncthreads_count(is_neg);   // publishes P / s_npos
    const int npos = s_npos;

    float acc = 0.f;
    if (is_neg && npos > 0) {
        const float cadd = 1.0f - d;    // margin - D[a,n]
        for (int q = 0; q < npos; q++) {
            float v = P[q] + cadd;
            acc += (v > 0.f) ? v : 0.f;
        }
    }

#pragma unroll
    for (int off = 16; off > 0; off >>= 1)
        acc += __shfl_down_sync(0xffffffffu, acc, off);
    if (lane == 0) s_red[wid] = (double)acc;
    __syncthreads();

    if (t == 0) {
        double tot = 0.0;
        for (int i = 0; i < 12; i++) tot += s_red[i];
        g_ptot[a] = tot;                              // distinct addresses:
        g_pcnt[a] = (ull)npos * (ull)nneg;            // plain STG, no atomics
        __threadfence();
        s_last = (atomicInc(&g_done, 0xffffffffu) == (unsigned)(B - 1));
    }
    __syncthreads();

    // --- Last block: parallel reduce the 384 partials and finalize. --------
    if (s_last) {
        double v = g_ptot[t];           // first touch, L2-coherent
        ull    c = g_pcnt[t];
#pragma unroll
        for (int off = 16; off > 0; off >>= 1) {
            v += __shfl_down_sync(0xffffffffu, v, off);
            c += __shfl_down_sync(0xffffffffu, c, off);
        }
        if (lane == 0) { s_red[wid] = v; s_redc[wid] = c; }
        __syncthreads();
        if (t == 0) {
            double tot = 0.0; ull cnt = 0ull;
            for (int i = 0; i < 12; i++) { tot += s_red[i]; cnt += s_redc[i]; }
            double mean = (cnt > 0) ? (tot / (double)cnt) : 0.0;
            if (out_size >= 1) out[0] = (float)mean;
            if (out_size >= 2) out[1] = (float)cnt;
        }
    }
}

extern "C" void kernel_launch(void* const* d_in, const int* in_sizes, int n_in,
                              void* d_out, int out_size) {
    const float* E = (const float*)d_in[0];
    const void* labels = d_in[1];
    float* out = (float*)d_out;

    dim3 grid(12, 12, SPLITK);
    k_gram<<<grid, 256>>>(E, labels);
    k_loss<<<B, B>>>(out, out_size);
}

// round 15
// speedup vs baseline: 2.7764x; 1.0889x over previous
#include <cuda_runtime.h>

#define B      384
#define DIM    1024
#define TS     64                // gram tile size
#define SPLITK 8
#define KPB    (DIM / SPLITK)    // 128 k per gram block
#define NIT    (KPB / 32)        // 4 iterations of k=32

typedef unsigned long long ull;

// Scratch in device globals (no allocations allowed).
__device__ float  g_Gp[SPLITK][B * B];   // partial Gram matrices per K-split
__device__ float  g_sqp[SPLITK][B];      // partial diagonals
__device__ int    g_lab[B];              // labels normalized to int32
__device__ double g_ptot[B];             // per-anchor loss partials
__device__ ull    g_pcnt[B];             // per-anchor triplet counts
__device__ unsigned int g_done;

// Staggered smem layout (float2/ull units): row j (0..63), 16 units per row,
// stride 17, extra bump every 16 rows. Row set {4tx+c} maps to bank-pairs
// (c + 4(tx&3) + (tx>>2)) mod 16 -> all 16 distinct: conflict-free LDS.64.
__device__ __forceinline__ int soff64(int j) {
    return j * 17 + (j >> 4);
}

// Packed dual fp32 FMA (SASS FFMA2) — only reachable via PTX.
__device__ __forceinline__ void ffma2(ull& acc, ull a, ull b) {
    asm("fma.rn.f32x2 %0, %1, %2, %0;" : "+l"(acc) : "l"(a), "l"(b));
}

__device__ __forceinline__ float unpack_sum(ull v) {
    float lo = __uint_as_float((unsigned)(v & 0xffffffffull));
    float hi = __uint_as_float((unsigned)(v >> 32));
    return lo + hi;   // even-k partial + odd-k partial
}

// ---------------------------------------------------------------------------
// Kernel 1: split-K Gram, 64x64 tiles, 4x4 register micro-tile over k-pairs.
// grid (6,6,8) = 288 blocks, 256 threads, 2 blocks/SM (single wave).
// ---------------------------------------------------------------------------
__global__ void __launch_bounds__(256, 2)
k_gram(const float* __restrict__ E, const void* __restrict__ labp) {
    __shared__ float2 SA[2][1090];
    __shared__ float2 SB[2][1090];

    const int tid = threadIdx.x;
    const int btx = blockIdx.x, bty = blockIdx.y, kz = blockIdx.z;
    const int row0 = bty * TS, col0 = btx * TS;

    if (btx == 0 && bty == 0 && kz == 0 && tid == 0) g_done = 0u;

    const int tx = tid & 15, ty = tid >> 4;
    const int li = tid >> 2;                   // loader row 0..63
    const int lq = tid & 3;                    // loader quarter (8 floats)
    const float* Ea = E + (size_t)(row0 + li) * DIM + kz * KPB + lq * 8;
    const float* Eb = E + (size_t)(col0 + li) * DIM + kz * KPB + lq * 8;

    const int st0 = soff64(li) + lq * 4;       // ull-unit store base
    int aoff[4], boff[4];
#pragma unroll
    for (int r = 0; r < 4; r++) {
        aoff[r] = soff64(4 * ty + r);
        boff[r] = soff64(4 * tx + r);
    }

    ull acc[4][4];
#pragma unroll
    for (int r = 0; r < 4; r++)
#pragma unroll
        for (int c = 0; c < 4; c++) acc[r][c] = 0ull;

    // 2-deep register prefetch: tile i lives in slot i&1 (2 float4 / panel).
    float4 ra[2][2], rb[2][2];
    ra[0][0] = *(const float4*)(Ea);       ra[0][1] = *(const float4*)(Ea + 4);
    rb[0][0] = *(const float4*)(Eb);       rb[0][1] = *(const float4*)(Eb + 4);
    ra[1][0] = *(const float4*)(Ea + 32);  ra[1][1] = *(const float4*)(Ea + 36);
    rb[1][0] = *(const float4*)(Eb + 32);  rb[1][1] = *(const float4*)(Eb + 36);

    SA[0][st0]     = make_float2(ra[0][0].x, ra[0][0].y);
    SA[0][st0 + 1] = make_float2(ra[0][0].z, ra[0][0].w);
    SA[0][st0 + 2] = make_float2(ra[0][1].x, ra[0][1].y);
    SA[0][st0 + 3] = make_float2(ra[0][1].z, ra[0][1].w);
    SB[0][st0]     = make_float2(rb[0][0].x, rb[0][0].y);
    SB[0][st0 + 1] = make_float2(rb[0][0].z, rb[0][0].w);
    SB[0][st0 + 2] = make_float2(rb[0][1].x, rb[0][1].y);
    SB[0][st0 + 3] = make_float2(rb[0][1].z, rb[0][1].w);
    __syncthreads();

    for (int it = 0; it < NIT; it++) {
        if (it + 1 < NIT) {                 // stage tile it+1 into other buffer
            const int nb = (it + 1) & 1;
            SA[nb][st0]     = make_float2(ra[nb][0].x, ra[nb][0].y);
            SA[nb][st0 + 1] = make_float2(ra[nb][0].z, ra[nb][0].w);
            SA[nb][st0 + 2] = make_float2(ra[nb][1].x, ra[nb][1].y);
            SA[nb][st0 + 3] = make_float2(ra[nb][1].z, ra[nb][1].w);
            SB[nb][st0]     = make_float2(rb[nb][0].x, rb[nb][0].y);
            SB[nb][st0 + 1] = make_float2(rb[nb][0].z, rb[nb][0].w);
            SB[nb][st0 + 2] = make_float2(rb[nb][1].x, rb[nb][1].y);
            SB[nb][st0 + 3] = make_float2(rb[nb][1].z, rb[nb][1].w);
        }
        if (it + 2 < NIT) {                 // LDG tile it+2 into freed slot
            const int s = it & 1;
            ra[s][0] = *(const float4*)(Ea + (it + 2) * 32);
            ra[s][1] = *(const float4*)(Ea + (it + 2) * 32 + 4);
            rb[s][0] = *(const float4*)(Eb + (it + 2) * 32);
            rb[s][1] = *(const float4*)(Eb + (it + 2) * 32 + 4);
        }
        const ull* SAu = (const ull*)SA[it & 1];
        const ull* SBu = (const ull*)SB[it & 1];
#pragma unroll
        for (int kk = 0; kk < 16; kk++) {
            ull av[4], bv[4];
#pragma unroll
            for (int r = 0; r < 4; r++) av[r] = SAu[aoff[r] + kk];
#pragma unroll
            for (int c = 0; c < 4; c++) bv[c] = SBu[boff[c] + kk];
#pragma unroll
            for (int r = 0; r < 4; r++)
#pragma unroll
                for (int c = 0; c < 4; c++)
                    ffma2(acc[r][c], av[r], bv[c]);
        }
        __syncthreads();
    }

    // Epilogue: 4 rows x float4 stores; explicit diag pick (no ptr indexing).
    float* Gz = g_Gp[kz];
#pragma unroll
    for (int r = 0; r < 4; r++) {
        const int gr = row0 + 4 * ty + r;
        const float v0 = unpack_sum(acc[r][0]);
        const float v1 = unpack_sum(acc[r][1]);
        const float v2 = unpack_sum(acc[r][2]);
        const float v3 = unpack_sum(acc[r][3]);
        *(float4*)(Gz + (size_t)gr * B + col0 + 4 * tx) =
            make_float4(v0, v1, v2, v3);
        if (btx == bty && tx == ty) {
            float dg = (r == 0) ? v0 : (r == 1) ? v1 : (r == 2) ? v2 : v3;
            g_sqp[kz][gr] = dg;             // diag partial: acc[r][r]
        }
    }

    // --- Label parse (block (0,0,0) only). Detect int64 vs int32 on the
    // first 1536 bytes: non-negative LE int64 => odd int32 words all zero.
    if (btx == 0 && bty == 0 && kz == 0) {
        const int* p32 = (const int*)labp;
        int ok = 1, ap = 0;
        for (int w = tid; w < B; w += 256) {
            int v = p32[w];
            if (w & 1) { if (v != 0) ok = 0; }
            else       { if (v > 0)  ap = 1; }
        }
        const int allz = __syncthreads_and(ok);
        const int anyp = __syncthreads_or(ap);
        const int is64 = allz && anyp;
        for (int j = tid; j < B; j += 256)
            g_lab[j] = is64 ? (int)((const long long*)labp)[j] : p32[j];
    }
}

// ---------------------------------------------------------------------------
// Kernel 2: triplet loss. One block per anchor, 384 threads. Per-block
// partials to distinct addresses; last block parallel-reduces them.
//   D[a,j]-D[a,n] = (sq_j - 2G[a,j]) - (sq_n - 2G[a,n]); sq_a cancels.
// ---------------------------------------------------------------------------
__global__ void __launch_bounds__(B)
k_loss(float* __restrict__ out, int out_size) {
    __shared__ float  P[B];
    __shared__ int    s_npos;
    __shared__ double s_red[12];
    __shared__ ull    s_redc[12];
    __shared__ int    s_last;

    const int a = blockIdx.x;
    const int t = threadIdx.x;
    const int lane = t & 31, wid = t >> 5;

    // Front-batch all independent loads (MLP hides the 8-way split).
    float gv = 0.f, sq = 0.f;
#pragma unroll
    for (int kz = 0; kz < SPLITK; kz++) {
        gv += g_Gp[kz][a * B + t];
        sq += g_sqp[kz][t];
    }
    const int lt = g_lab[t];
    const int la = g_lab[a];            // warp-uniform broadcast load

    if (t == 0) s_npos = 0;
    __syncthreads();

    const float d = sq - 2.0f * gv;
    const int ispos = (t > a) && (lt == la);

    // Warp-aggregated compaction of positives into P.
    unsigned m = __ballot_sync(0xffffffffu, ispos);
    if (m) {
        int base = 0;
        if (lane == 0) base = atomicAdd(&s_npos, __popc(m));
        base = __shfl_sync(0xffffffffu, base, 0);
        if (ispos) P[base + __popc(m & ((1u << lane) - 1u))] = d;
    }
    const int is_neg = (lt != la);
    const int nneg = __syncthreads_count(is_neg);   // publishes P / s_npos
    const int npos = s_npos;

    float acc = 0.f;
    if (is_neg && npos > 0) {
        const float cadd = 1.0f - d;    // margin - D[a,n]
        for (int q = 0; q < npos; q++) {
            float v = P[q] + cadd;
            acc += (v > 0.f) ? v : 0.f;
        }
    }

#pragma unroll
    for (int off = 16; off > 0; off >>= 1)
        acc += __shfl_down_sync(0xffffffffu, acc, off);
    if (lane == 0) s_red[wid] = (double)acc;
    __syncthreads();

    if (t == 0) {
        double tot = 0.0;
        for (int i = 0; i < 12; i++) tot += s_red[i];
        g_ptot[a] = tot;                              // distinct addresses:
        g_pcnt[a] = (ull)npos * (ull)nneg;            // plain STG, no atomics
        __threadfence();
        s_last = (atomicInc(&g_done, 0xffffffffu) == (unsigned)(B - 1));
    }
    __syncthreads();

    // --- Last block: parallel reduce the 384 partials and finalize. --------
    if (s_last) {
        double v = g_ptot[t];
        ull    c = g_pcnt[t];
#pragma unroll
        for (int off = 16; off > 0; off >>= 1) {
            v += __shfl_down_sync(0xffffffffu, v, off);
            c += __shfl_down_sync(0xffffffffu, c, off);
        }
        if (lane == 0) { s_red[wid] = v; s_redc[wid] = c; }
        __syncthreads();
        if (t == 0) {
            double tot = 0.0; ull cnt = 0ull;
            for (int i = 0; i < 12; i++) { tot += s_red[i]; cnt += s_redc[i]; }
            double mean = (cnt > 0) ? (tot / (double)cnt) : 0.0;
            if (out_size >= 1) out[0] = (float)mean;
            if (out_size >= 2) out[1] = (float)cnt;
        }
    }
}

extern "C" void kernel_launch(void* const* d_in, const int* in_sizes, int n_in,
                              void* d_out, int out_size) {
    const float* E = (const float*)d_in[0];
    const void* labels = d_in[1];
    float* out = (float*)d_out;

    k_gram<<<dim3(6, 6, SPLITK), 256>>>(E, labels);
    k_loss<<<B, B>>>(out, out_size);
}